// round 7
// baseline (speedup 1.0000x reference)
#include <cuda_runtime.h>
#include <cuda_fp16.h>
#include <cstdint>
#include <cstddef>

#define S_LEN 512
#define HSTRIDE 132
#define XSTRIDE 68

// fp16 weights, full-k octet layout: addr = (i*128 + j)*8 + e, k = i*8 + e.
// 64-k mats: i<8 (8192 halves); 128-k mats: i<16 (16384 halves).
#define OFF_WIN0S 0
#define OFF_WG0S  8192
#define OFF_WG0H  16384
#define OFF_WREC0 32768
#define OFF_WIN1  49152
#define OFF_WG1X  65536
#define OFF_WG1H  81920
#define OFF_WREC1 98304
#define WH_TOTAL  114688

__device__ __align__(16) __half g_Wh[WH_TOTAL];
// ctx mats stay fp32, k-quad layout: addr = kq*512 + j*4 + e
__device__ __align__(16) float g_Wc[2 * 4096];

// ---------------- packed fp32x2 helpers (SASS FFMA2, PTX-only) ----------------
__device__ __forceinline__ unsigned long long ffma2(unsigned long long a,
                                                    unsigned long long b,
                                                    unsigned long long c) {
    unsigned long long d;
    asm("fma.rn.f32x2 %0, %1, %2, %3;" : "=l"(d) : "l"(a), "l"(b), "l"(c));
    return d;
}
__device__ __forceinline__ float redu2(unsigned long long v) {
    float lo, hi;
    asm("mov.b64 {%0, %1}, %2;" : "=f"(lo), "=f"(hi) : "l"(v));
    return lo + hi;
}
// expand 2 fp16 -> packed fp32x2 u64
__device__ __forceinline__ unsigned long long h2pack(unsigned int u) {
    __half2 h = *reinterpret_cast<const __half2*>(&u);
    float2 f = __half22float2(h);
    unsigned long long r;
    asm("mov.b64 %0, {%1, %2};" : "=l"(r) : "f"(f.x), "f"(f.y));
    return r;
}
__device__ __forceinline__ float sigm(float x) {
    return __fdividef(1.0f, 1.0f + __expf(-x));
}
__device__ __forceinline__ float fast_tanh(float x) {
    float ax = fabsf(x);
    float e = __expf(ax + ax);
    float t = 1.0f - __fdividef(2.0f, e + 1.0f);
    return copysignf(t, x);
}

// ---------------- weight layout prep ----------------
__global__ void __launch_bounds__(256) prep_weights(
    const float* __restrict__ Win0, const float* __restrict__ Wg0,
    const float* __restrict__ Wrec0, const float* __restrict__ Win1,
    const float* __restrict__ Wrec1, const float* __restrict__ Wg1) {
    int idx = blockIdx.x * 256 + threadIdx.x;
    if (idx < 16384) {  // 64-k mats: Win0 seq / Wg0 seq
        int m = idx >> 13;
        int a = idx & 8191;
        int e = a & 7, t = a >> 3;
        int j = t & 127, i = t >> 7;
        int k = i * 8 + e;
        float v = m ? Wg0[j * 224 + k] : Win0[j * 96 + k];
        g_Wh[idx] = __float2half_rn(v);
    } else if (idx < WH_TOTAL) {  // 128-k mats
        int m = (idx - 16384) >> 14;
        int a = (idx - 16384) & 16383;
        int e = a & 7, t = a >> 3;
        int j = t & 127, i = t >> 7;
        int k = i * 8 + e;
        float v;
        switch (m) {
            case 0: v = Wg0[j * 224 + 96 + k]; break;
            case 1: v = Wrec0[j * 128 + k]; break;
            case 2: v = Win1[j * 128 + k]; break;
            case 3: v = Wg1[j * 256 + k]; break;
            case 4: v = Wg1[j * 256 + 128 + k]; break;
            default: v = Wrec1[j * 128 + k]; break;
        }
        g_Wh[idx] = __float2half_rn(v);
    } else if (idx < WH_TOTAL + 8192) {  // ctx parts, fp32 k-quad
        int r = idx - WH_TOTAL;
        int m = r >> 12;
        int a = r & 4095;
        int j = (a >> 2) & 127;
        int k = ((a >> 9) << 2) | (a & 3);
        g_Wc[r] = m ? Wg0[j * 224 + 64 + k] : Win0[j * 96 + 64 + k];
    }
}

// Full-k dual mat-vec for 2 batches (this lane's pair). No cross-lane reduction.
// x points at the batch-pair base (xs + bh*2*XS). ITERS = k/8.
template <int ITERS, int XS>
__device__ __forceinline__ void dualmv2(const __half* __restrict__ Wa,
                                        const __half* __restrict__ Wb,
                                        const float* __restrict__ x,
                                        float ra[2], float rb[2]) {
    unsigned long long a0 = 0, a1 = 0, c0 = 0, c1 = 0;
#pragma unroll
    for (int i = 0; i < ITERS; ++i) {
        uint4 wra = __ldg(reinterpret_cast<const uint4*>(Wa + (size_t)i * 1024));
        uint4 wrb = __ldg(reinterpret_cast<const uint4*>(Wb + (size_t)i * 1024));
        unsigned long long wa0 = h2pack(wra.x), wa1 = h2pack(wra.y);
        unsigned long long wa2 = h2pack(wra.z), wa3 = h2pack(wra.w);
        unsigned long long wb0 = h2pack(wrb.x), wb1 = h2pack(wrb.y);
        unsigned long long wb2 = h2pack(wrb.z), wb3 = h2pack(wrb.w);
        ulonglong2 x00 = *reinterpret_cast<const ulonglong2*>(x + i * 8);
        ulonglong2 x01 = *reinterpret_cast<const ulonglong2*>(x + i * 8 + 4);
        ulonglong2 x10 = *reinterpret_cast<const ulonglong2*>(x + XS + i * 8);
        ulonglong2 x11 = *reinterpret_cast<const ulonglong2*>(x + XS + i * 8 + 4);
        a0 = ffma2(wa0, x00.x, a0);
        a0 = ffma2(wa1, x00.y, a0);
        a0 = ffma2(wa2, x01.x, a0);
        a0 = ffma2(wa3, x01.y, a0);
        a1 = ffma2(wa0, x10.x, a1);
        a1 = ffma2(wa1, x10.y, a1);
        a1 = ffma2(wa2, x11.x, a1);
        a1 = ffma2(wa3, x11.y, a1);
        c0 = ffma2(wb0, x00.x, c0);
        c0 = ffma2(wb1, x00.y, c0);
        c0 = ffma2(wb2, x01.x, c0);
        c0 = ffma2(wb3, x01.y, c0);
        c1 = ffma2(wb0, x10.x, c1);
        c1 = ffma2(wb1, x10.y, c1);
        c1 = ffma2(wb2, x11.x, c1);
        c1 = ffma2(wb3, x11.y, c1);
    }
    ra[0] = redu2(a0);
    ra[1] = redu2(a1);
    rb[0] = redu2(c0);
    rb[1] = redu2(c1);
}

// RK4 for one cell; cu/nx ping-pong h buffers (1 bar per sub-phase). Each thread
// owns (row jl, batches bh*2 / bh*2+1). Last sub-phase stores h0r when WRITE_H0.
template <bool WRITE_H0>
__device__ __forceinline__ void rk4_cell(const __half* __restrict__ Wg,
                                         const __half* __restrict__ Wr, float itau,
                                         const float* xin, const float* xg, float* hb,
                                         const float* h0r, float*& cu, float*& nx,
                                         int boff, int jl) {
    float ka[2] = {0.f, 0.f};
    float ht[2] = {hb[0], hb[1]};
#pragma unroll
    for (int sub = 0; sub < 4; ++sub) {
        float ra[2], rb[2];
        dualmv2<16, HSTRIDE>(Wg, Wr, cu + boff, ra, rb);
        const float kw = (sub == 0 || sub == 3) ? 1.0f : 2.0f;
        const float cv = (sub < 2) ? 0.5f : 1.0f;
#pragma unroll
        for (int bb = 0; bb < 2; ++bb) {
            float gate = sigm(fast_tanh(ra[bb] + xg[bb]));
            float kv = fmaf(gate, rb[bb], fmaf(-ht[bb], itau, xin[bb]));
            ka[bb] = fmaf(kw, kv, ka[bb]);
            float nh = (sub < 3) ? fmaf(cv, kv, hb[bb])
                                 : fast_tanh(fmaf(ka[bb], 0.16666667f, hb[bb]));
            ht[bb] = nh;
            nx[boff + bb * HSTRIDE + jl] = (sub == 3 && WRITE_H0) ? h0r[bb] : nh;
        }
        __syncthreads();
        float* t = cu; cu = nx; nx = t;
    }
    hb[0] = ht[0];
    hb[1] = ht[1];
}

// ---------------- persistent recurrence: 128 CTAs x 256 threads ----------------
// Warp w covers rows jl = w*16 + (lane&15); lane bh = lane>>4 owns batch pair
// {bh*2, bh*2+1} across the full k (no cross-lane reduction).
__global__ void __launch_bounds__(256, 1)
ltc_recurrent(const float* __restrict__ seq, const float* __restrict__ ctx,
              const float* __restrict__ tau0, const float* __restrict__ bg0,
              const float* __restrict__ tau1, const float* __restrict__ bg1,
              const float* __restrict__ W1, const float* __restrict__ b1,
              const float* __restrict__ W2, const float* __restrict__ b2,
              float* __restrict__ out) {
    __shared__ __align__(16) float hhA[4 * HSTRIDE];
    __shared__ __align__(16) float hhB[4 * HSTRIDE];
    __shared__ __align__(16) float xs[4 * XSTRIDE];
    __shared__ __align__(16) float xc[4 * 32];
    __shared__ __align__(16) float st0[512];
    __shared__ __align__(16) float st1[512];
    const int tid = threadIdx.x;
    const int lane = tid & 31;
    const int w = tid >> 5;
    const int bh = lane >> 4;
    const int jl = (w << 4) + (lane & 15);
    const int boff = bh * 2 * HSTRIDE;
    const int xboff = bh * 2 * XSTRIDE;
    const int b0g = blockIdx.x * 4;

    const float it0 = __fdividef(1.0f, log1pf(__expf(tau0[jl])) + 1.0f);
    const float it1 = __fdividef(1.0f, log1pf(__expf(tau1[jl])) + 1.0f);
    const float bg1j = bg1[jl];

    const int wo = jl * 8;
    const __half* Win0s = g_Wh + OFF_WIN0S + wo;
    const __half* Wg0s  = g_Wh + OFF_WG0S  + wo;
    const __half* Wg0h  = g_Wh + OFF_WG0H  + wo;
    const __half* Wrec0 = g_Wh + OFF_WREC0 + wo;
    const __half* Win1  = g_Wh + OFF_WIN1  + wo;
    const __half* Wg1x  = g_Wh + OFF_WG1X  + wo;
    const __half* Wg1h  = g_Wh + OFF_WG1H  + wo;
    const __half* Wrec1 = g_Wh + OFF_WREC1 + wo;

    // ---- step-invariant ctx projection (threads 0-127, fp32 k-quad) ----
    if (tid < 128) {
        int b = tid >> 5, i = tid & 31;
        xc[b * 32 + i] = ctx[(size_t)(b0g + b) * 32 + i];
    }
    __syncthreads();
    if (tid < 128) {
        const int j = tid;
        const float* Wa = g_Wc + j * 4;
        const float* Wb = g_Wc + 4096 + j * 4;
        unsigned long long a[4] = {0, 0, 0, 0}, c[4] = {0, 0, 0, 0};
#pragma unroll
        for (int kq = 0; kq < 8; ++kq) {
            ulonglong2 wa = __ldg(reinterpret_cast<const ulonglong2*>(Wa + kq * 512));
            ulonglong2 wb = __ldg(reinterpret_cast<const ulonglong2*>(Wb + kq * 512));
#pragma unroll
            for (int b = 0; b < 4; ++b) {
                ulonglong2 xv = *reinterpret_cast<const ulonglong2*>(xc + b * 32 + kq * 4);
                a[b] = ffma2(wa.x, xv.x, a[b]);
                a[b] = ffma2(wa.y, xv.y, a[b]);
                c[b] = ffma2(wb.x, xv.x, c[b]);
                c[b] = ffma2(wb.y, xv.y, c[b]);
            }
        }
        const float bg0j = bg0[j];
#pragma unroll
        for (int b = 0; b < 4; ++b) {
            st0[b * 128 + j] = redu2(a[b]);
            st1[b * 128 + j] = redu2(c[b]) + bg0j;
        }
    }
    __syncthreads();
    float xinc[2], xgc[2];
#pragma unroll
    for (int bb = 0; bb < 2; ++bb) {
        xinc[bb] = st0[(bh * 2 + bb) * 128 + jl];
        xgc[bb] = st1[(bh * 2 + bb) * 128 + jl];
    }

    float h0r[2] = {0.f, 0.f}, h1r[2] = {0.f, 0.f};
    float* cu = hhA;
    float* nx = hhB;
    for (int t = tid; t < 4 * HSTRIDE; t += 256) hhA[t] = 0.f;

    for (int s = 0; s < S_LEN; ++s) {
        // load this step's seq slice: xs[b*XSTRIDE + k], k<64
        {
            int b = tid >> 6, k = tid & 63;
            xs[b * XSTRIDE + k] = seq[((size_t)(b0g + b) * S_LEN + s) * 64 + k];
        }
        __syncthreads();

        // cell-0 input projections (seq part) + ctx base
        float xin0[2], xg0[2];
        dualmv2<8, XSTRIDE>(Win0s, Wg0s, xs + xboff, xin0, xg0);
#pragma unroll
        for (int bb = 0; bb < 2; ++bb) { xin0[bb] += xinc[bb]; xg0[bb] += xgc[bb]; }

        // cell 0 (cu holds h0; leaves h0_new in cu and h0r)
        rk4_cell<false>(Wg0h, Wrec0, it0, xin0, xg0, h0r, nullptr, cu, nx, boff, jl);

        // cell-1 input projections from h0_new; stage h1 into nx
        float xin1[2], xg1[2];
        dualmv2<16, HSTRIDE>(Win1, Wg1x, cu + boff, xin1, xg1);
#pragma unroll
        for (int bb = 0; bb < 2; ++bb) {
            xg1[bb] += bg1j;
            nx[boff + bb * HSTRIDE + jl] = h1r[bb];
        }
        __syncthreads();
        { float* t = cu; cu = nx; nx = t; }

        // cell 1 (last sub writes h0_new back for the next step's cell 0)
        rk4_cell<true>(Wg1h, Wrec1, it1, xin1, xg1, h1r, h0r, cu, nx, boff, jl);
    }

    // ---- classifier: sigmoid(relu(h1 @ W1^T + b1) @ W2^T + b2) ----
    __syncthreads();
#pragma unroll
    for (int bb = 0; bb < 2; ++bb) st0[(bh * 2 + bb) * 128 + jl] = h1r[bb];
    __syncthreads();
    if (tid < 128) {
        const int b = tid >> 5, ln = tid & 31;
        float a0 = b1[ln], a1 = b1[ln + 32];
        const float* hv = st0 + b * 128;
        const float* w0 = W1 + ln * 128;
        const float* w1 = W1 + (ln + 32) * 128;
#pragma unroll 8
        for (int k = 0; k < 128; ++k) {
            float h = hv[k];
            a0 = fmaf(h, w0[k], a0);
            a1 = fmaf(h, w1[k], a1);
        }
        a0 = fmaxf(a0, 0.f);
        a1 = fmaxf(a1, 0.f);
        float p = a0 * __ldg(W2 + ln) + a1 * __ldg(W2 + ln + 32);
#pragma unroll
        for (int off = 16; off; off >>= 1) p += __shfl_xor_sync(0xffffffffu, p, off);
        if (ln == 0) out[b0g + b] = sigm(p + b2[0]);
    }
}

extern "C" void kernel_launch(void* const* d_in, const int* in_sizes, int n_in,
                              void* d_out, int out_size) {
    const float* seq   = (const float*)d_in[0];
    const float* ctx   = (const float*)d_in[1];
    const float* tau0  = (const float*)d_in[2];
    const float* Win0  = (const float*)d_in[3];
    const float* Wrec0 = (const float*)d_in[4];
    const float* Wg0   = (const float*)d_in[5];
    const float* bg0   = (const float*)d_in[6];
    const float* tau1  = (const float*)d_in[7];
    const float* Win1  = (const float*)d_in[8];
    const float* Wrec1 = (const float*)d_in[9];
    const float* Wg1   = (const float*)d_in[10];
    const float* bg1   = (const float*)d_in[11];
    const float* W1    = (const float*)d_in[12];
    const float* b1    = (const float*)d_in[13];
    const float* W2    = (const float*)d_in[14];
    const float* b2    = (const float*)d_in[15];
    float* out = (float*)d_out;

    prep_weights<<<(WH_TOTAL + 8192 + 255) / 256, 256>>>(Win0, Wg0, Wrec0, Win1,
                                                         Wrec1, Wg1);
    ltc_recurrent<<<128, 256>>>(seq, ctx, tau0, bg0, tau1, bg1, W1, b1, W2, b2, out);
}

// round 8
// speedup vs baseline: 1.4759x; 1.4759x over previous
#include <cuda_runtime.h>
#include <cuda_fp16.h>
#include <cstdint>
#include <cstddef>

#define S_LEN 512
#define HSTRIDE 128
#define XSTRIDE 64

// fp16 weight offsets (half elements).
// 64-k mats:  addr = ((i*2+half)*128 + j)*8 + e,  k = half*32 + i*8 + e, i<4
// 128-k mats: addr = ((i*2+half)*128 + j)*8 + e,  k = half*64 + i*8 + e, i<8
#define OFF_WIN0S 0
#define OFF_WG0S  8192
#define OFF_WG0H  16384
#define OFF_WREC0 32768
#define OFF_WIN1  49152
#define OFF_WG1X  65536
#define OFF_WG1H  81920
#define OFF_WREC1 98304
#define WH_TOTAL  114688

__device__ __align__(16) __half g_Wh[WH_TOTAL];
// ctx mats stay fp32, k-quad layout: addr = kq*512 + j*4 + e
__device__ __align__(16) float g_Wc[2 * 4096];

// ---------------- packed fp32x2 helpers (SASS FFMA2, PTX-only) ----------------
__device__ __forceinline__ unsigned long long ffma2(unsigned long long a,
                                                    unsigned long long b,
                                                    unsigned long long c) {
    unsigned long long d;
    asm("fma.rn.f32x2 %0, %1, %2, %3;" : "=l"(d) : "l"(a), "l"(b), "l"(c));
    return d;
}
__device__ __forceinline__ float redu2(unsigned long long v) {
    float lo, hi;
    asm("mov.b64 {%0, %1}, %2;" : "=f"(lo), "=f"(hi) : "l"(v));
    return lo + hi;
}
// expand 2 fp16 -> packed fp32x2 u64
__device__ __forceinline__ unsigned long long h2pack(unsigned int u) {
    __half2 h = *reinterpret_cast<const __half2*>(&u);
    float2 f = __half22float2(h);
    unsigned long long r;
    asm("mov.b64 %0, {%1, %2};" : "=l"(r) : "f"(f.x), "f"(f.y));
    return r;
}
__device__ __forceinline__ float sigm(float x) {
    return __fdividef(1.0f, 1.0f + __expf(-x));
}
__device__ __forceinline__ float fast_tanh(float x) {
    float ax = fabsf(x);
    float e = __expf(ax + ax);
    float t = 1.0f - __fdividef(2.0f, e + 1.0f);
    return copysignf(t, x);
}
// reduce packed acc + combine the two k-halves (lanes l, l^16)
__device__ __forceinline__ float redsum(unsigned long long v) {
    float r = redu2(v);
    r += __shfl_xor_sync(0xffffffffu, r, 16);
    return r;
}

// ---------------- weight layout prep ----------------
__global__ void __launch_bounds__(256) prep_weights(
    const float* __restrict__ Win0, const float* __restrict__ Wg0,
    const float* __restrict__ Wrec0, const float* __restrict__ Win1,
    const float* __restrict__ Wrec1, const float* __restrict__ Wg1) {
    int idx = blockIdx.x * 256 + threadIdx.x;
    if (idx < 16384) {  // 64-k mats: Win0 seq / Wg0 seq
        int m = idx >> 13;
        int a = idx & 8191;
        int e = a & 7, t = a >> 3;
        int j = t & 127, t2 = t >> 7;
        int hf = t2 & 1, i = t2 >> 1;
        int k = hf * 32 + i * 8 + e;
        float v = m ? Wg0[j * 224 + k] : Win0[j * 96 + k];
        g_Wh[idx] = __float2half_rn(v);
    } else if (idx < WH_TOTAL) {  // 128-k mats
        int m = (idx - 16384) >> 14;
        int a = (idx - 16384) & 16383;
        int e = a & 7, t = a >> 3;
        int j = t & 127, t2 = t >> 7;
        int hf = t2 & 1, i = t2 >> 1;
        int k = hf * 64 + i * 8 + e;
        float v;
        switch (m) {
            case 0: v = Wg0[j * 224 + 96 + k]; break;
            case 1: v = Wrec0[j * 128 + k]; break;
            case 2: v = Win1[j * 128 + k]; break;
            case 3: v = Wg1[j * 256 + k]; break;
            case 4: v = Wg1[j * 256 + 128 + k]; break;
            default: v = Wrec1[j * 128 + k]; break;
        }
        g_Wh[idx] = __float2half_rn(v);
    } else if (idx < WH_TOTAL + 8192) {  // ctx parts, fp32 k-quad
        int r = idx - WH_TOTAL;
        int m = r >> 12;
        int a = r & 4095;
        int j = (a >> 2) & 127;
        int k = ((a >> 9) << 2) | (a & 3);
        g_Wc[r] = m ? Wg0[j * 224 + 64 + k] : Win0[j * 96 + 64 + k];
    }
}

// Half-split dual mat-vec, fp16 weights (no register caching — for the
// once-per-step projection phases). ITERS = (k/2)/8.
template <int ITERS, int XS>
__device__ __forceinline__ void dualmv_h(const __half* __restrict__ Wa,
                                         const __half* __restrict__ Wb,
                                         const float* __restrict__ x,
                                         float ra[4], float rb[4]) {
    unsigned long long a[4] = {0, 0, 0, 0};
    unsigned long long c[4] = {0, 0, 0, 0};
#pragma unroll
    for (int i = 0; i < ITERS; ++i) {
        uint4 wra = __ldg(reinterpret_cast<const uint4*>(Wa + (size_t)i * 2048));
        uint4 wrb = __ldg(reinterpret_cast<const uint4*>(Wb + (size_t)i * 2048));
        unsigned long long wa0 = h2pack(wra.x), wa1 = h2pack(wra.y);
        unsigned long long wa2 = h2pack(wra.z), wa3 = h2pack(wra.w);
        unsigned long long wb0 = h2pack(wrb.x), wb1 = h2pack(wrb.y);
        unsigned long long wb2 = h2pack(wrb.z), wb3 = h2pack(wrb.w);
#pragma unroll
        for (int b = 0; b < 4; ++b) {
            ulonglong2 x0 = *reinterpret_cast<const ulonglong2*>(x + b * XS + i * 16);
            ulonglong2 x1 = *reinterpret_cast<const ulonglong2*>(x + b * XS + i * 16 + 4);
            a[b] = ffma2(wa0, x0.x, a[b]);
            a[b] = ffma2(wa1, x0.y, a[b]);
            a[b] = ffma2(wa2, x1.x, a[b]);
            a[b] = ffma2(wa3, x1.y, a[b]);
            c[b] = ffma2(wb0, x0.x, c[b]);
            c[b] = ffma2(wb1, x0.y, c[b]);
            c[b] = ffma2(wb2, x1.x, c[b]);
            c[b] = ffma2(wb3, x1.y, c[b]);
        }
    }
#pragma unroll
    for (int b = 0; b < 4; ++b) {
        ra[b] = redsum(a[b]);
        rb[b] = redsum(c[b]);
    }
}

// RK4 for one cell with REGISTER-CACHED weights: this thread's 64-half slices
// of Wg and Wr are loaded + converted to packed fp32x2 ONCE, then reused across
// all 4 RK4 sub-phases (removes 48 LDG + 384 cvt per thread per cell).
// The sub loop stays rolled so the W registers stay live across iterations.
template <bool WRITE_H0>
__device__ __forceinline__ void rk4_cell(const __half* __restrict__ Wg,
                                         const __half* __restrict__ Wr, float itau,
                                         const float* xin, const float* xg, float* hb,
                                         const float* h0r, float*& cu, float*& nx,
                                         int xoff, int hslot, int half) {
    unsigned long long wg[32], wr[32];
#pragma unroll
    for (int i = 0; i < 8; ++i) {
        uint4 ua = __ldg(reinterpret_cast<const uint4*>(Wg + (size_t)i * 2048));
        wg[i * 4 + 0] = h2pack(ua.x);
        wg[i * 4 + 1] = h2pack(ua.y);
        wg[i * 4 + 2] = h2pack(ua.z);
        wg[i * 4 + 3] = h2pack(ua.w);
        uint4 ub = __ldg(reinterpret_cast<const uint4*>(Wr + (size_t)i * 2048));
        wr[i * 4 + 0] = h2pack(ub.x);
        wr[i * 4 + 1] = h2pack(ub.y);
        wr[i * 4 + 2] = h2pack(ub.z);
        wr[i * 4 + 3] = h2pack(ub.w);
    }
    float ka[4] = {0.f, 0.f, 0.f, 0.f};
    float ht[4] = {hb[0], hb[1], hb[2], hb[3]};
    for (int sub = 0; sub < 4; ++sub) {  // rolled: W regs persist
        unsigned long long a[4] = {0, 0, 0, 0};
        unsigned long long c[4] = {0, 0, 0, 0};
        const float* x = cu + xoff;
#pragma unroll
        for (int i = 0; i < 8; ++i) {
#pragma unroll
            for (int b = 0; b < 4; ++b) {
                ulonglong2 x0 =
                    *reinterpret_cast<const ulonglong2*>(x + b * HSTRIDE + i * 16);
                ulonglong2 x1 =
                    *reinterpret_cast<const ulonglong2*>(x + b * HSTRIDE + i * 16 + 4);
                a[b] = ffma2(wg[i * 4 + 0], x0.x, a[b]);
                a[b] = ffma2(wg[i * 4 + 1], x0.y, a[b]);
                a[b] = ffma2(wg[i * 4 + 2], x1.x, a[b]);
                a[b] = ffma2(wg[i * 4 + 3], x1.y, a[b]);
                c[b] = ffma2(wr[i * 4 + 0], x0.x, c[b]);
                c[b] = ffma2(wr[i * 4 + 1], x0.y, c[b]);
                c[b] = ffma2(wr[i * 4 + 2], x1.x, c[b]);
                c[b] = ffma2(wr[i * 4 + 3], x1.y, c[b]);
            }
        }
        const float kw = (sub == 0 || sub == 3) ? 1.0f : 2.0f;
        const float cv = (sub < 2) ? 0.5f : 1.0f;
#pragma unroll
        for (int b = 0; b < 4; ++b) {
            float gate = sigm(fast_tanh(redsum(a[b]) + xg[b]));
            float kv = fmaf(gate, redsum(c[b]), fmaf(-ht[b], itau, xin[b]));
            ka[b] = fmaf(kw, kv, ka[b]);
            float nh = (sub < 3) ? fmaf(cv, kv, hb[b])
                                 : fast_tanh(fmaf(ka[b], 0.16666667f, hb[b]));
            ht[b] = nh;
            if (half == 0)
                nx[b * HSTRIDE + hslot] = (sub == 3 && WRITE_H0) ? h0r[b] : nh;
        }
        __syncthreads();
        float* t = cu;
        cu = nx;
        nx = t;
    }
    hb[0] = ht[0];
    hb[1] = ht[1];
    hb[2] = ht[2];
    hb[3] = ht[3];
}

// ---------------- persistent recurrence: 128 CTAs x 256 threads ----------------
// Warp w covers rows jl = w*16 + (lane&15); lane half = lane>>4 covers one k-half.
__global__ void __launch_bounds__(256, 1)
ltc_recurrent(const float* __restrict__ seq, const float* __restrict__ ctx,
              const float* __restrict__ tau0, const float* __restrict__ bg0,
              const float* __restrict__ tau1, const float* __restrict__ bg1,
              const float* __restrict__ W1, const float* __restrict__ b1,
              const float* __restrict__ W2, const float* __restrict__ b2,
              float* __restrict__ out) {
    __shared__ __align__(16) float hhA[4 * HSTRIDE];
    __shared__ __align__(16) float hhB[4 * HSTRIDE];
    __shared__ __align__(16) float xs[4 * XSTRIDE];
    __shared__ __align__(16) float xc[4 * 32];
    __shared__ __align__(16) float st0[512];
    __shared__ __align__(16) float st1[512];
    const int tid = threadIdx.x;
    const int lane = tid & 31;
    const int w = tid >> 5;
    const int half = lane >> 4;
    const int jl = (w << 4) + (lane & 15);
    const int xoff = half * 8;
    // smem slot of h[jl]: slot = i*16 + half_j*8 + e for jl = half_j*64+i*8+e
    const int hslot = (((jl >> 3) & 7) << 4) + ((jl >> 6) << 3) + (jl & 7);
    const int b0g = blockIdx.x * 4;

    const float it0 = __fdividef(1.0f, log1pf(__expf(tau0[jl])) + 1.0f);
    const float it1 = __fdividef(1.0f, log1pf(__expf(tau1[jl])) + 1.0f);
    const float bg1j = bg1[jl];

    const int wo = (half * 128 + jl) * 8;
    const __half* Win0s = g_Wh + OFF_WIN0S + wo;
    const __half* Wg0s  = g_Wh + OFF_WG0S  + wo;
    const __half* Wg0h  = g_Wh + OFF_WG0H  + wo;
    const __half* Wrec0 = g_Wh + OFF_WREC0 + wo;
    const __half* Win1  = g_Wh + OFF_WIN1  + wo;
    const __half* Wg1x  = g_Wh + OFF_WG1X  + wo;
    const __half* Wg1h  = g_Wh + OFF_WG1H  + wo;
    const __half* Wrec1 = g_Wh + OFF_WREC1 + wo;

    // ---- step-invariant ctx projection (threads 0-127, fp32 k-quad) ----
    if (tid < 128) {
        int b = tid >> 5, i = tid & 31;
        xc[b * 32 + i] = ctx[(size_t)(b0g + b) * 32 + i];
    }
    __syncthreads();
    if (tid < 128) {
        const int j = tid;
        const float* Wa = g_Wc + j * 4;
        const float* Wb = g_Wc + 4096 + j * 4;
        unsigned long long a[4] = {0, 0, 0, 0}, c[4] = {0, 0, 0, 0};
#pragma unroll
        for (int kq = 0; kq < 8; ++kq) {
            ulonglong2 wa = __ldg(reinterpret_cast<const ulonglong2*>(Wa + kq * 512));
            ulonglong2 wb = __ldg(reinterpret_cast<const ulonglong2*>(Wb + kq * 512));
#pragma unroll
            for (int b = 0; b < 4; ++b) {
                ulonglong2 xv = *reinterpret_cast<const ulonglong2*>(xc + b * 32 + kq * 4);
                a[b] = ffma2(wa.x, xv.x, a[b]);
                a[b] = ffma2(wa.y, xv.y, a[b]);
                c[b] = ffma2(wb.x, xv.x, c[b]);
                c[b] = ffma2(wb.y, xv.y, c[b]);
            }
        }
        const float bg0j = bg0[j];
#pragma unroll
        for (int b = 0; b < 4; ++b) {
            st0[b * 128 + j] = redu2(a[b]);
            st1[b * 128 + j] = redu2(c[b]) + bg0j;
        }
    }
    __syncthreads();
    float xinc[4], xgc[4];
#pragma unroll
    for (int b = 0; b < 4; ++b) {
        xinc[b] = st0[b * 128 + jl];
        xgc[b] = st1[b * 128 + jl];
    }

    float h0r[4] = {0.f, 0.f, 0.f, 0.f}, h1r[4] = {0.f, 0.f, 0.f, 0.f};
    float* cu = hhA;
    float* nx = hhB;
    hhA[tid] = 0.f;
    hhA[256 + tid] = 0.f;

    for (int s = 0; s < S_LEN; ++s) {
        // load this step's seq slice into xs (slot = i*16 + half*8 + e, k<64)
        {
            int b = tid >> 6, k = tid & 63;
            float v = seq[((size_t)(b0g + b) * S_LEN + s) * 64 + k];
            int sl = (((k >> 3) & 3) << 4) + ((k >> 5) << 3) + (k & 7);
            xs[b * XSTRIDE + sl] = v;
        }
        __syncthreads();

        // cell-0 input projections (seq part) + ctx base
        float xin0[4], xg0[4];
        dualmv_h<4, XSTRIDE>(Win0s, Wg0s, xs + xoff, xin0, xg0);
#pragma unroll
        for (int b = 0; b < 4; ++b) { xin0[b] += xinc[b]; xg0[b] += xgc[b]; }

        // cell 0 (cu holds h0; leaves h0_new in cu and h0r)
        rk4_cell<false>(Wg0h, Wrec0, it0, xin0, xg0, h0r, nullptr, cu, nx, xoff,
                        hslot, half);

        // cell-1 input projections from h0_new; stage h1 into nx
        float xin1[4], xg1[4];
        dualmv_h<8, HSTRIDE>(Win1, Wg1x, cu + xoff, xin1, xg1);
#pragma unroll
        for (int b = 0; b < 4; ++b) {
            xg1[b] += bg1j;
            if (half == 0) nx[b * HSTRIDE + hslot] = h1r[b];
        }
        __syncthreads();
        { float* t = cu; cu = nx; nx = t; }

        // cell 1 (last sub writes h0_new back for the next step's cell 0)
        rk4_cell<true>(Wg1h, Wrec1, it1, xin1, xg1, h1r, h0r, cu, nx, xoff,
                       hslot, half);
    }

    // ---- classifier: sigmoid(relu(h1 @ W1^T + b1) @ W2^T + b2) ----
    __syncthreads();
    if (half == 0) {
#pragma unroll
        for (int b = 0; b < 4; ++b) st0[b * 128 + jl] = h1r[b];
    }
    __syncthreads();
    if (tid < 128) {
        const int b = tid >> 5, ln = tid & 31;
        float a0 = b1[ln], a1 = b1[ln + 32];
        const float* hv = st0 + b * 128;
        const float* w0 = W1 + ln * 128;
        const float* w1 = W1 + (ln + 32) * 128;
#pragma unroll 8
        for (int k = 0; k < 128; ++k) {
            float h = hv[k];
            a0 = fmaf(h, w0[k], a0);
            a1 = fmaf(h, w1[k], a1);
        }
        a0 = fmaxf(a0, 0.f);
        a1 = fmaxf(a1, 0.f);
        float p = a0 * __ldg(W2 + ln) + a1 * __ldg(W2 + ln + 32);
#pragma unroll
        for (int off = 16; off; off >>= 1) p += __shfl_xor_sync(0xffffffffu, p, off);
        if (ln == 0) out[b0g + b] = sigm(p + b2[0]);
    }
}

extern "C" void kernel_launch(void* const* d_in, const int* in_sizes, int n_in,
                              void* d_out, int out_size) {
    const float* seq   = (const float*)d_in[0];
    const float* ctx   = (const float*)d_in[1];
    const float* tau0  = (const float*)d_in[2];
    const float* Win0  = (const float*)d_in[3];
    const float* Wrec0 = (const float*)d_in[4];
    const float* Wg0   = (const float*)d_in[5];
    const float* bg0   = (const float*)d_in[6];
    const float* tau1  = (const float*)d_in[7];
    const float* Win1  = (const float*)d_in[8];
    const float* Wrec1 = (const float*)d_in[9];
    const float* Wg1   = (const float*)d_in[10];
    const float* bg1   = (const float*)d_in[11];
    const float* W1    = (const float*)d_in[12];
    const float* b1    = (const float*)d_in[13];
    const float* W2    = (const float*)d_in[14];
    const float* b2    = (const float*)d_in[15];
    float* out = (float*)d_out;

    prep_weights<<<(WH_TOTAL + 8192 + 255) / 256, 256>>>(Win0, Wg0, Wrec0, Win1,
                                                         Wrec1, Wg1);
    ltc_recurrent<<<128, 256>>>(seq, ctx, tau0, bg0, tau1, bg1, W1, b1, W2, b2, out);
}

// round 9
// speedup vs baseline: 1.6848x; 1.1416x over previous
#include <cuda_runtime.h>
#include <cuda_fp16.h>
#include <cstdint>
#include <cstddef>

#define S_LEN 512
#define HSTRIDE 128
#define XSTRIDE 64

// fp16 weight offsets (half elements).
// 64-k mats:  addr = ((i*2+half)*128 + j)*8 + e,  k = half*32 + i*8 + e, i<4
// 128-k mats: addr = ((i*2+half)*128 + j)*8 + e,  k = half*64 + i*8 + e, i<8
#define OFF_WIN0S 0
#define OFF_WG0S  8192
#define OFF_WG0H  16384
#define OFF_WREC0 32768
#define OFF_WIN1  49152
#define OFF_WG1X  65536
#define OFF_WG1H  81920
#define OFF_WREC1 98304
#define WH_TOTAL  114688

__device__ __align__(16) __half g_Wh[WH_TOTAL];
// ctx mats stay fp32, k-quad layout: addr = kq*512 + j*4 + e
__device__ __align__(16) float g_Wc[2 * 4096];

// ---------------- packed fp32x2 helpers (SASS FFMA2, PTX-only) ----------------
__device__ __forceinline__ unsigned long long ffma2(unsigned long long a,
                                                    unsigned long long b,
                                                    unsigned long long c) {
    unsigned long long d;
    asm("fma.rn.f32x2 %0, %1, %2, %3;" : "=l"(d) : "l"(a), "l"(b), "l"(c));
    return d;
}
__device__ __forceinline__ float redu2(unsigned long long v) {
    float lo, hi;
    asm("mov.b64 {%0, %1}, %2;" : "=f"(lo), "=f"(hi) : "l"(v));
    return lo + hi;
}
// expand 2 fp16 -> packed fp32x2 u64
__device__ __forceinline__ unsigned long long h2pack(unsigned int u) {
    __half2 h = *reinterpret_cast<const __half2*>(&u);
    float2 f = __half22float2(h);
    unsigned long long r;
    asm("mov.b64 %0, {%1, %2};" : "=l"(r) : "f"(f.x), "f"(f.y));
    return r;
}
__device__ __forceinline__ float sigm(float x) {
    return __fdividef(1.0f, 1.0f + __expf(-x));
}
__device__ __forceinline__ float fast_tanh(float x) {
    float ax = fabsf(x);
    float e = __expf(ax + ax);
    float t = 1.0f - __fdividef(2.0f, e + 1.0f);
    return copysignf(t, x);
}
// gate = sigmoid(tanh(z)). tanh via exp; sigmoid of t in [-1,1] via degree-7
// odd polynomial (Taylor with adjusted c7; max abs err ~1.1e-5 on [-1,1]).
__device__ __forceinline__ float gate_fn(float z) {
    float t = fast_tanh(z);
    float t2 = t * t;
    float p = fmaf(t2, -2.00134e-4f, 2.0833333e-3f);
    p = fmaf(t2, p, -2.0833334e-2f);
    p = fmaf(t2, p, 0.25f);
    return fmaf(t, p, 0.5f);
}
// Combine partial dots across the two k-halves (lanes l, l^16). a[0..3] are
// this lane's k-half partials for batches 0..3; own[bb] gets the FULL dot for
// batch 2*half+bb. Each lane sends the partner's batches: 4 shfl total per
// dual-accumulator group instead of 8.
__device__ __forceinline__ void combine_own(const unsigned long long a[4], int half,
                                            float own[2]) {
#pragma unroll
    for (int bb = 0; bb < 2; ++bb) {
        float mine = redu2(half ? a[2 + bb] : a[bb]);
        float send = redu2(half ? a[bb] : a[2 + bb]);
        float recv = __shfl_xor_sync(0xffffffffu, send, 16);
        own[bb] = mine + recv;
    }
}

// ---------------- weight layout prep ----------------
__global__ void __launch_bounds__(256) prep_weights(
    const float* __restrict__ Win0, const float* __restrict__ Wg0,
    const float* __restrict__ Wrec0, const float* __restrict__ Win1,
    const float* __restrict__ Wrec1, const float* __restrict__ Wg1) {
    int idx = blockIdx.x * 256 + threadIdx.x;
    if (idx < 16384) {  // 64-k mats: Win0 seq / Wg0 seq
        int m = idx >> 13;
        int a = idx & 8191;
        int e = a & 7, t = a >> 3;
        int j = t & 127, t2 = t >> 7;
        int hf = t2 & 1, i = t2 >> 1;
        int k = hf * 32 + i * 8 + e;
        float v = m ? Wg0[j * 224 + k] : Win0[j * 96 + k];
        g_Wh[idx] = __float2half_rn(v);
    } else if (idx < WH_TOTAL) {  // 128-k mats
        int m = (idx - 16384) >> 14;
        int a = (idx - 16384) & 16383;
        int e = a & 7, t = a >> 3;
        int j = t & 127, t2 = t >> 7;
        int hf = t2 & 1, i = t2 >> 1;
        int k = hf * 64 + i * 8 + e;
        float v;
        switch (m) {
            case 0: v = Wg0[j * 224 + 96 + k]; break;
            case 1: v = Wrec0[j * 128 + k]; break;
            case 2: v = Win1[j * 128 + k]; break;
            case 3: v = Wg1[j * 256 + k]; break;
            case 4: v = Wg1[j * 256 + 128 + k]; break;
            default: v = Wrec1[j * 128 + k]; break;
        }
        g_Wh[idx] = __float2half_rn(v);
    } else if (idx < WH_TOTAL + 8192) {  // ctx parts, fp32 k-quad
        int r = idx - WH_TOTAL;
        int m = r >> 12;
        int a = r & 4095;
        int j = (a >> 2) & 127;
        int k = ((a >> 9) << 2) | (a & 3);
        g_Wc[r] = m ? Wg0[j * 224 + 64 + k] : Win0[j * 96 + 64 + k];
    }
}

// Half-split dual mat-vec, fp16 weights; returns FULL dots for this lane's two
// OWNED batches only (combine_own). ITERS = (k/2)/8.
template <int ITERS, int XS>
__device__ __forceinline__ void dualmv_own(const __half* __restrict__ Wa,
                                           const __half* __restrict__ Wb,
                                           const float* __restrict__ x, int half,
                                           float ra[2], float rb[2]) {
    unsigned long long a[4] = {0, 0, 0, 0};
    unsigned long long c[4] = {0, 0, 0, 0};
#pragma unroll
    for (int i = 0; i < ITERS; ++i) {
        uint4 wra = __ldg(reinterpret_cast<const uint4*>(Wa + (size_t)i * 2048));
        uint4 wrb = __ldg(reinterpret_cast<const uint4*>(Wb + (size_t)i * 2048));
        unsigned long long wa0 = h2pack(wra.x), wa1 = h2pack(wra.y);
        unsigned long long wa2 = h2pack(wra.z), wa3 = h2pack(wra.w);
        unsigned long long wb0 = h2pack(wrb.x), wb1 = h2pack(wrb.y);
        unsigned long long wb2 = h2pack(wrb.z), wb3 = h2pack(wrb.w);
#pragma unroll
        for (int b = 0; b < 4; ++b) {
            ulonglong2 x0 = *reinterpret_cast<const ulonglong2*>(x + b * XS + i * 16);
            ulonglong2 x1 = *reinterpret_cast<const ulonglong2*>(x + b * XS + i * 16 + 4);
            a[b] = ffma2(wa0, x0.x, a[b]);
            a[b] = ffma2(wa1, x0.y, a[b]);
            a[b] = ffma2(wa2, x1.x, a[b]);
            a[b] = ffma2(wa3, x1.y, a[b]);
            c[b] = ffma2(wb0, x0.x, c[b]);
            c[b] = ffma2(wb1, x0.y, c[b]);
            c[b] = ffma2(wb2, x1.x, c[b]);
            c[b] = ffma2(wb3, x1.y, c[b]);
        }
    }
    combine_own(a, half, ra);
    combine_own(c, half, rb);
}

// RK4 for one cell. Each lane owns (rows via warp, batches {2*half, 2*half+1})
// for the elementwise update; both halves store their own 2 h values. cu/nx
// ping-pong (1 bar per sub-phase). Last sub stores h0r when WRITE_H0.
template <bool WRITE_H0>
__device__ __forceinline__ void rk4_cell(const __half* __restrict__ Wg,
                                         const __half* __restrict__ Wr, float itau,
                                         const float* xin, const float* xg, float* hb,
                                         const float* h0r, float*& cu, float*& nx,
                                         int xoff, int hslot, int half) {
    float ka[2] = {0.f, 0.f};
    float ht[2] = {hb[0], hb[1]};
#pragma unroll
    for (int sub = 0; sub < 4; ++sub) {
        float ra[2], rb[2];
        dualmv_own<8, HSTRIDE>(Wg, Wr, cu + xoff, half, ra, rb);
        const float kw = (sub == 0 || sub == 3) ? 1.0f : 2.0f;
        const float cv = (sub < 2) ? 0.5f : 1.0f;
#pragma unroll
        for (int bb = 0; bb < 2; ++bb) {
            float gate = gate_fn(ra[bb] + xg[bb]);
            float kv = fmaf(gate, rb[bb], fmaf(-ht[bb], itau, xin[bb]));
            ka[bb] = fmaf(kw, kv, ka[bb]);
            float nh = (sub < 3) ? fmaf(cv, kv, hb[bb])
                                 : fast_tanh(fmaf(ka[bb], 0.16666667f, hb[bb]));
            ht[bb] = nh;
            nx[(2 * half + bb) * HSTRIDE + hslot] =
                (sub == 3 && WRITE_H0) ? h0r[bb] : nh;
        }
        __syncthreads();
        float* t = cu;
        cu = nx;
        nx = t;
    }
    hb[0] = ht[0];
    hb[1] = ht[1];
}

// ---------------- persistent recurrence: 128 CTAs x 256 threads ----------------
// Warp w covers rows jl = w*16 + (lane&15); lane half = lane>>4 covers one k-half
// in the matmuls and owns batches {2*half, 2*half+1} in the elementwise update.
__global__ void __launch_bounds__(256, 1)
ltc_recurrent(const float* __restrict__ seq, const float* __restrict__ ctx,
              const float* __restrict__ tau0, const float* __restrict__ bg0,
              const float* __restrict__ tau1, const float* __restrict__ bg1,
              const float* __restrict__ W1, const float* __restrict__ b1,
              const float* __restrict__ W2, const float* __restrict__ b2,
              float* __restrict__ out) {
    __shared__ __align__(16) float hhA[4 * HSTRIDE];
    __shared__ __align__(16) float hhB[4 * HSTRIDE];
    __shared__ __align__(16) float xs[2][4 * XSTRIDE];  // double-buffered x
    __shared__ __align__(16) float xc[4 * 32];
    __shared__ __align__(16) float st0[512];
    __shared__ __align__(16) float st1[512];
    const int tid = threadIdx.x;
    const int lane = tid & 31;
    const int w = tid >> 5;
    const int half = lane >> 4;
    const int jl = (w << 4) + (lane & 15);
    const int xoff = half * 8;
    // smem slot of h[jl]: slot = i*16 + half_j*8 + e for jl = half_j*64+i*8+e
    const int hslot = (((jl >> 3) & 7) << 4) + ((jl >> 6) << 3) + (jl & 7);
    const int b0g = blockIdx.x * 4;

    const float it0 = __fdividef(1.0f, log1pf(__expf(tau0[jl])) + 1.0f);
    const float it1 = __fdividef(1.0f, log1pf(__expf(tau1[jl])) + 1.0f);
    const float bg1j = bg1[jl];

    const int wo = (half * 128 + jl) * 8;
    const __half* Win0s = g_Wh + OFF_WIN0S + wo;
    const __half* Wg0s  = g_Wh + OFF_WG0S  + wo;
    const __half* Wg0h  = g_Wh + OFF_WG0H  + wo;
    const __half* Wrec0 = g_Wh + OFF_WREC0 + wo;
    const __half* Win1  = g_Wh + OFF_WIN1  + wo;
    const __half* Wg1x  = g_Wh + OFF_WG1X  + wo;
    const __half* Wg1h  = g_Wh + OFF_WG1H  + wo;
    const __half* Wrec1 = g_Wh + OFF_WREC1 + wo;

    // per-thread x-element for (pre)loads: batch xb, feature xk
    const int xb = tid >> 6;
    const int xk = tid & 63;
    const int xslot = xb * XSTRIDE + ((((xk >> 3) & 3) << 4) + ((xk >> 5) << 3) + (xk & 7));
    const float* seq_elem = seq + ((size_t)(b0g + xb) * S_LEN) * 64 + xk;

    // ---- step-invariant ctx projection (threads 0-127, fp32 k-quad) ----
    if (tid < 128) {
        int b = tid >> 5, i = tid & 31;
        xc[b * 32 + i] = ctx[(size_t)(b0g + b) * 32 + i];
    }
    __syncthreads();
    if (tid < 128) {
        const int j = tid;
        const float* Wa = g_Wc + j * 4;
        const float* Wb = g_Wc + 4096 + j * 4;
        unsigned long long a[4] = {0, 0, 0, 0}, c[4] = {0, 0, 0, 0};
#pragma unroll
        for (int kq = 0; kq < 8; ++kq) {
            ulonglong2 wa = __ldg(reinterpret_cast<const ulonglong2*>(Wa + kq * 512));
            ulonglong2 wb = __ldg(reinterpret_cast<const ulonglong2*>(Wb + kq * 512));
#pragma unroll
            for (int b = 0; b < 4; ++b) {
                ulonglong2 xv = *reinterpret_cast<const ulonglong2*>(xc + b * 32 + kq * 4);
                a[b] = ffma2(wa.x, xv.x, a[b]);
                a[b] = ffma2(wa.y, xv.y, a[b]);
                c[b] = ffma2(wb.x, xv.x, c[b]);
                c[b] = ffma2(wb.y, xv.y, c[b]);
            }
        }
        const float bg0j = bg0[j];
#pragma unroll
        for (int b = 0; b < 4; ++b) {
            st0[b * 128 + j] = redu2(a[b]);
            st1[b * 128 + j] = redu2(c[b]) + bg0j;
        }
    }
    __syncthreads();
    float xinc[2], xgc[2];
#pragma unroll
    for (int bb = 0; bb < 2; ++bb) {
        xinc[bb] = st0[(2 * half + bb) * 128 + jl];
        xgc[bb] = st1[(2 * half + bb) * 128 + jl];
    }

    float h0r[2] = {0.f, 0.f}, h1r[2] = {0.f, 0.f};
    float* cu = hhA;
    float* nx = hhB;
    hhA[tid] = 0.f;
    hhA[256 + tid] = 0.f;
    // preload x(0)
    xs[0][xslot] = seq_elem[0];
    __syncthreads();

    int p = 0;
    for (int s = 0; s < S_LEN; ++s) {
        // prefetch x(s+1) into a register early (hidden behind cell 0)
        float xpv = 0.f;
        if (s + 1 < S_LEN) xpv = seq_elem[(size_t)(s + 1) * 64];

        // cell-0 input projections (seq part) + ctx base
        float xin0[2], xg0[2];
        dualmv_own<4, XSTRIDE>(Win0s, Wg0s, xs[p] + xoff, half, xin0, xg0);
#pragma unroll
        for (int bb = 0; bb < 2; ++bb) { xin0[bb] += xinc[bb]; xg0[bb] += xgc[bb]; }

        // cell 0 (cu holds h0; leaves h0_new in cu and h0r)
        rk4_cell<false>(Wg0h, Wrec0, it0, xin0, xg0, h0r, nullptr, cu, nx, xoff,
                        hslot, half);

        // stage next step's x; ordering to next-step readers is covered by the
        // staging bar below + cell-1's sub-phase bars
        if (s + 1 < S_LEN) xs[p ^ 1][xslot] = xpv;

        // cell-1 input projections from h0_new; stage h1 into nx
        float xin1[2], xg1[2];
        dualmv_own<8, HSTRIDE>(Win1, Wg1x, cu + xoff, half, xin1, xg1);
#pragma unroll
        for (int bb = 0; bb < 2; ++bb) {
            xg1[bb] += bg1j;
            nx[(2 * half + bb) * HSTRIDE + hslot] = h1r[bb];
        }
        __syncthreads();
        { float* t = cu; cu = nx; nx = t; }

        // cell 1 (last sub writes h0_new back for the next step's cell 0)
        rk4_cell<true>(Wg1h, Wrec1, it1, xin1, xg1, h1r, h0r, cu, nx, xoff,
                       hslot, half);
        p ^= 1;
    }

    // ---- classifier: sigmoid(relu(h1 @ W1^T + b1) @ W2^T + b2) ----
    __syncthreads();
#pragma unroll
    for (int bb = 0; bb < 2; ++bb) st0[(2 * half + bb) * 128 + jl] = h1r[bb];
    __syncthreads();
    if (tid < 128) {
        const int b = tid >> 5, ln = tid & 31;
        float a0 = b1[ln], a1 = b1[ln + 32];
        const float* hv = st0 + b * 128;
        const float* w0 = W1 + ln * 128;
        const float* w1 = W1 + (ln + 32) * 128;
#pragma unroll 8
        for (int k = 0; k < 128; ++k) {
            float h = hv[k];
            a0 = fmaf(h, w0[k], a0);
            a1 = fmaf(h, w1[k], a1);
        }
        a0 = fmaxf(a0, 0.f);
        a1 = fmaxf(a1, 0.f);
        float pr = a0 * __ldg(W2 + ln) + a1 * __ldg(W2 + ln + 32);
#pragma unroll
        for (int off = 16; off; off >>= 1) pr += __shfl_xor_sync(0xffffffffu, pr, off);
        if (ln == 0) out[b0g + b] = sigm(pr + b2[0]);
    }
}

extern "C" void kernel_launch(void* const* d_in, const int* in_sizes, int n_in,
                              void* d_out, int out_size) {
    const float* seq   = (const float*)d_in[0];
    const float* ctx   = (const float*)d_in[1];
    const float* tau0  = (const float*)d_in[2];
    const float* Win0  = (const float*)d_in[3];
    const float* Wrec0 = (const float*)d_in[4];
    const float* Wg0   = (const float*)d_in[5];
    const float* bg0   = (const float*)d_in[6];
    const float* tau1  = (const float*)d_in[7];
    const float* Win1  = (const float*)d_in[8];
    const float* Wrec1 = (const float*)d_in[9];
    const float* Wg1   = (const float*)d_in[10];
    const float* bg1   = (const float*)d_in[11];
    const float* W1    = (const float*)d_in[12];
    const float* b1    = (const float*)d_in[13];
    const float* W2    = (const float*)d_in[14];
    const float* b2    = (const float*)d_in[15];
    float* out = (float*)d_out;

    prep_weights<<<(WH_TOTAL + 8192 + 255) / 256, 256>>>(Win0, Wg0, Wrec0, Win1,
                                                         Wrec1, Wg1);
    ltc_recurrent<<<128, 256>>>(seq, ctx, tau0, bg0, tau1, bg1, W1, b1, W2, b2, out);
}